// round 3
// baseline (speedup 1.0000x reference)
#include <cuda_runtime.h>
#include <math.h>

// ---------------- scratch (device globals; no allocation allowed) -------------
#define BATCH 8192
#define DIN   256
#define H1    512
#define H2    256
#define DOUT  64

__device__ float g_h1[BATCH * H1];        // 16.8 MB
__device__ float g_h2[BATCH * H2];        //  8.4 MB
__device__ float g_out[BATCH * DOUT];     //  2.1 MB  (row-major [B][64])
__device__ float g_nT[DOUT * BATCH];      //  2.1 MB  (col-major normed: [64][B])

__device__ __forceinline__ float tanh_fast(float x)
{
    float y;
    asm("tanh.approx.f32 %0, %1;" : "=f"(y) : "f"(x));
    return y;
}

// ---------------- GEMM: C[M,N] = act(A[M,K] @ W[N,K]^T + b) ------------------
// BM=BN=128, BK=8, 256 threads, 8x8 micro-tile.
template <int K, bool TANH>
__global__ void __launch_bounds__(256) gemm_tanh_kernel(
    const float* __restrict__ A, const float* __restrict__ W,
    const float* __restrict__ bias, float* __restrict__ C, int N)
{
    __shared__ __align__(16) float As[8][132];
    __shared__ __align__(16) float Ws[8][132];

    const int t  = threadIdx.x;
    const int tx = t & 15;
    const int ty = t >> 4;
    const int m0 = blockIdx.x * 128;
    const int n0 = blockIdx.y * 128;

    const int lrow = t >> 1;          // 0..127
    const int lk   = (t & 1) * 4;     // 0 or 4

    const float* Ag = A + (size_t)(m0 + lrow) * K + lk;
    const float* Wg = W + (size_t)(n0 + lrow) * K + lk;

    float acc[8][8];
#pragma unroll
    for (int r = 0; r < 8; r++)
#pragma unroll
        for (int c = 0; c < 8; c++) acc[r][c] = 0.0f;

    for (int kk = 0; kk < K; kk += 8) {
        float4 av = *reinterpret_cast<const float4*>(Ag + kk);
        float4 wv = *reinterpret_cast<const float4*>(Wg + kk);
        __syncthreads();
        As[lk + 0][lrow] = av.x; As[lk + 1][lrow] = av.y;
        As[lk + 2][lrow] = av.z; As[lk + 3][lrow] = av.w;
        Ws[lk + 0][lrow] = wv.x; Ws[lk + 1][lrow] = wv.y;
        Ws[lk + 2][lrow] = wv.z; Ws[lk + 3][lrow] = wv.w;
        __syncthreads();
#pragma unroll
        for (int k = 0; k < 8; k++) {
            float a[8], b[8];
#pragma unroll
            for (int r = 0; r < 8; r++) a[r] = As[k][tx + 16 * r];
#pragma unroll
            for (int c = 0; c < 8; c++) b[c] = Ws[k][ty + 16 * c];
#pragma unroll
            for (int r = 0; r < 8; r++)
#pragma unroll
                for (int c = 0; c < 8; c++) acc[r][c] += a[r] * b[c];
        }
    }

#pragma unroll
    for (int r = 0; r < 8; r++) {
        int m = m0 + tx + 16 * r;
#pragma unroll
        for (int c = 0; c < 8; c++) {
            int n = n0 + ty + 16 * c;
            float v = acc[r][c] + bias[n];
            if (TANH) v = tanh_fast(v);
            C[(size_t)m * N + n] = v;
        }
    }
}

// ------------- GEMM3 + bias + row-normalize; writes out and normed^T ----------
// Block: 64 rows x 64 cols, K=256, BK=16, 256 threads, 4x4 micro-tile.
__global__ void __launch_bounds__(256) out_norm_kernel(
    const float* __restrict__ A,   // g_h2 [B][256]
    const float* __restrict__ W3,  // [64][256]
    const float* __restrict__ b3)
{
    __shared__ __align__(16) float As[16][68];
    __shared__ __align__(16) float Ws[16][68];
    __shared__ __align__(16) float outS[64][68];
    __shared__ float rs[64];

    const int t  = threadIdx.x;
    const int tx = t & 15;
    const int ty = t >> 4;
    const int i0 = blockIdx.x * 64;
    const int K  = 256;

    const int lrow = t >> 2;          // 0..63
    const int lk   = (t & 3) * 4;     // 0,4,8,12

    float acc[4][4];
#pragma unroll
    for (int r = 0; r < 4; r++)
#pragma unroll
        for (int c = 0; c < 4; c++) acc[r][c] = 0.0f;

    for (int kk = 0; kk < K; kk += 16) {
        float4 av = *reinterpret_cast<const float4*>(A + (size_t)(i0 + lrow) * K + kk + lk);
        float4 wv = *reinterpret_cast<const float4*>(W3 + (size_t)lrow * K + kk + lk);
        __syncthreads();
        As[lk + 0][lrow] = av.x; As[lk + 1][lrow] = av.y;
        As[lk + 2][lrow] = av.z; As[lk + 3][lrow] = av.w;
        Ws[lk + 0][lrow] = wv.x; Ws[lk + 1][lrow] = wv.y;
        Ws[lk + 2][lrow] = wv.z; Ws[lk + 3][lrow] = wv.w;
        __syncthreads();
#pragma unroll
        for (int k = 0; k < 16; k++) {
            float a[4], b[4];
#pragma unroll
            for (int r = 0; r < 4; r++) a[r] = As[k][tx + 16 * r];
#pragma unroll
            for (int c = 0; c < 4; c++) b[c] = Ws[k][ty + 16 * c];
#pragma unroll
            for (int r = 0; r < 4; r++)
#pragma unroll
                for (int c = 0; c < 4; c++) acc[r][c] += a[r] * b[c];
        }
    }

#pragma unroll
    for (int r = 0; r < 4; r++)
#pragma unroll
        for (int c = 0; c < 4; c++)
            outS[tx + 16 * r][ty + 16 * c] = acc[r][c] + b3[ty + 16 * c];
    __syncthreads();

    if (t < 64) {
        float s = 0.0f;
#pragma unroll
        for (int c = 0; c < 64; c++) { float v = outS[t][c]; s += v * v; }
        rs[t] = 1.0f / (sqrtf(s) + 1e-12f);
    }
    __syncthreads();

    // out: coalesced over columns
#pragma unroll
    for (int q = 0; q < 16; q++) {
        int idx = t + 256 * q;
        int i = idx >> 6, c = idx & 63;
        g_out[(size_t)(i0 + i) * DOUT + c] = outS[i][c];
    }
    // normed^T: coalesced over rows (batch index contiguous)
#pragma unroll
    for (int q = 0; q < 16; q++) {
        int idx = t + 256 * q;
        int c = idx >> 6, i = idx & 63;
        g_nT[(size_t)c * BATCH + i0 + i] = outS[i][c] * rs[i];
    }
}

// -------------------- zero output ---------------------------------------------
__global__ void zero_kernel(float* __restrict__ p, int n)
{
    int i = blockIdx.x * blockDim.x + threadIdx.x;
    if (i < n) p[i] = 0.0f;
}

// ------------- fused fidelity + masked accumulate ------------------------------
// 128x128 tile, 256 threads, 8x8 micro-tile (FMA-bound: 1 B/FMA from smem).
// result += sum_{j : (n_i . n_j)^2 >= 0.9, i != j} out[j]   via sparse bitmask.
#define JSPLIT 8
__global__ void __launch_bounds__(256, 2) fid_kernel(float* __restrict__ res)
{
    __shared__ __align__(16) float NiT[64][128];              // 32 KB, k-major
    __shared__ __align__(16) float NjT[64][128];              // 32 KB, k-major
    __shared__ unsigned long long maskS[128][2];              // 2 KB

    const int t  = threadIdx.x;
    const int tx = t & 15;       // i micro-row base = 8*tx
    const int ty = t >> 4;       // j micro-col base = 8*ty
    const int i0 = blockIdx.x * 128;
    const int jb = blockIdx.y * (BATCH / JSPLIT);
    const int je = jb + (BATCH / JSPLIT);

    // load Ni^T tile (64 k-rows x 128 i): contiguous float4 over batch dim
#pragma unroll
    for (int q = 0; q < 8; q++) {
        int idx = t + 256 * q;        // float4 index, 32 per k-row
        int k  = idx >> 5;
        int i4 = (idx & 31) * 4;
        float4 v = *reinterpret_cast<const float4*>(
            g_nT + (size_t)k * BATCH + i0 + i4);
        *reinterpret_cast<float4*>(&NiT[k][i4]) = v;
    }

    const int my_i = t >> 1;          // accumulate ownership: row 0..127
    const int cb   = (t & 1) * 32;    // 32-col slice
    float facc[32];
#pragma unroll
    for (int c = 0; c < 32; c++) facc[c] = 0.0f;

    for (int j0 = jb; j0 < je; j0 += 128) {
        __syncthreads();              // previous accumulate done with maskS/NjT
        if (t < 128) { maskS[t][0] = 0ULL; maskS[t][1] = 0ULL; }
#pragma unroll
        for (int q = 0; q < 8; q++) {
            int idx = t + 256 * q;
            int k  = idx >> 5;
            int j4 = (idx & 31) * 4;
            float4 v = *reinterpret_cast<const float4*>(
                g_nT + (size_t)k * BATCH + j0 + j4);
            *reinterpret_cast<float4*>(&NjT[k][j4]) = v;
        }
        __syncthreads();

        float acc[8][8];
#pragma unroll
        for (int r = 0; r < 8; r++)
#pragma unroll
            for (int c = 0; c < 8; c++) acc[r][c] = 0.0f;

#pragma unroll 4
        for (int k = 0; k < 64; k++) {
            float4 a0 = *reinterpret_cast<const float4*>(&NiT[k][8 * tx]);
            float4 a1 = *reinterpret_cast<const float4*>(&NiT[k][8 * tx + 4]);
            float4 b0 = *reinterpret_cast<const float4*>(&NjT[k][8 * ty]);
            float4 b1 = *reinterpret_cast<const float4*>(&NjT[k][8 * ty + 4]);
            float a[8] = {a0.x, a0.y, a0.z, a0.w, a1.x, a1.y, a1.z, a1.w};
            float b[8] = {b0.x, b0.y, b0.z, b0.w, b1.x, b1.y, b1.z, b1.w};
#pragma unroll
            for (int r = 0; r < 8; r++)
#pragma unroll
                for (int c = 0; c < 8; c++) acc[r][c] += a[r] * b[c];
        }

        // build adjacency bitmask for this 128x128 tile
#pragma unroll
        for (int r = 0; r < 8; r++) {
            unsigned byte = 0;
            int gi = i0 + 8 * tx + r;
#pragma unroll
            for (int c = 0; c < 8; c++) {
                int gj = j0 + 8 * ty + c;
                float d = acc[r][c];
                if (d * d >= 0.9f && gi != gj) byte |= (1u << c);
            }
            if (byte) {
                int word  = ty >> 3;
                int shift = (ty & 7) * 8;
                atomicOr(&maskS[8 * tx + r][word],
                         (unsigned long long)byte << shift);
            }
        }
        __syncthreads();

        // sparse accumulate: only rows with set bits touch g_out
#pragma unroll
        for (int w = 0; w < 2; w++) {
            unsigned long long m = maskS[my_i][w];
            while (m) {
                int j = __ffsll((long long)m) - 1;
                m &= m - 1;
                const float4* op = reinterpret_cast<const float4*>(
                    g_out + (size_t)(j0 + 64 * w + j) * DOUT + cb);
#pragma unroll
                for (int c4 = 0; c4 < 8; c4++) {
                    float4 v = op[c4];
                    facc[4 * c4 + 0] += v.x;
                    facc[4 * c4 + 1] += v.y;
                    facc[4 * c4 + 2] += v.z;
                    facc[4 * c4 + 3] += v.w;
                }
            }
        }
    }

    float* rp = res + (size_t)(i0 + my_i) * DOUT + cb;
#pragma unroll
    for (int c = 0; c < 32; c++) atomicAdd(&rp[c], facc[c]);
}

// ------------------------------- launch ----------------------------------------
extern "C" void kernel_launch(void* const* d_in, const int* in_sizes, int n_in,
                              void* d_out, int out_size)
{
    const float* x  = (const float*)d_in[0];
    const float* W1 = (const float*)d_in[1];
    const float* b1 = (const float*)d_in[2];
    const float* W2 = (const float*)d_in[3];
    const float* b2 = (const float*)d_in[4];
    const float* W3 = (const float*)d_in[5];
    const float* b3 = (const float*)d_in[6];
    float* out = (float*)d_out;

    float *h1p, *h2p;
    cudaGetSymbolAddress((void**)&h1p, g_h1);
    cudaGetSymbolAddress((void**)&h2p, g_h2);

    // h1 = tanh(x @ W1^T + b1)   [8192, 512]
    gemm_tanh_kernel<DIN, true><<<dim3(BATCH / 128, H1 / 128), 256>>>(
        x, W1, b1, h1p, H1);
    // h2 = tanh(h1 @ W2^T + b2)  [8192, 256]
    gemm_tanh_kernel<H1, true><<<dim3(BATCH / 128, H2 / 128), 256>>>(
        h1p, W2, b2, h2p, H2);
    // out3 = h2 @ W3^T + b3; also writes normed^T
    out_norm_kernel<<<BATCH / 64, 256>>>(h2p, W3, b3);
    // zero result
    int n = BATCH * DOUT;
    zero_kernel<<<(n + 255) / 256, 256>>>(out, n);
    // fidelity mask + sparse accumulate
    fid_kernel<<<dim3(BATCH / 128, JSPLIT), 256>>>(out);
}

// round 4
// speedup vs baseline: 1.0600x; 1.0600x over previous
#include <cuda_runtime.h>
#include <cuda_bf16.h>
#include <math.h>

// ---------------- scratch (device globals; no allocation allowed) -------------
#define BATCH 8192
#define DIN   256
#define H1    512
#define H2    256
#define DOUT  64

__device__ float g_h1[BATCH * H1];              // 16.8 MB
__device__ float g_h2[BATCH * H2];              //  8.4 MB
__device__ float g_out[BATCH * DOUT];           //  2.1 MB  row-major [B][64]
__device__ float g_nrm[BATCH * DOUT];           //  2.1 MB  fp32 normed, row-major
__device__ __nv_bfloat16 g_nB[BATCH * DOUT];    //  1.0 MB  bf16 normed, row-major

__device__ __forceinline__ float tanh_fast(float x)
{
    float y;
    asm("tanh.approx.f32 %0, %1;" : "=f"(y) : "f"(x));
    return y;
}

__device__ __forceinline__ unsigned smem_u32(const void* p)
{
    return (unsigned)__cvta_generic_to_shared(p);
}

// ---------------- GEMM: C[M,N] = act(A[M,K] @ W[N,K]^T + b) ------------------
template <int K, bool TANH>
__global__ void __launch_bounds__(256) gemm_tanh_kernel(
    const float* __restrict__ A, const float* __restrict__ W,
    const float* __restrict__ bias, float* __restrict__ C, int N)
{
    __shared__ __align__(16) float As[8][132];
    __shared__ __align__(16) float Ws[8][132];

    const int t  = threadIdx.x;
    const int tx = t & 15;
    const int ty = t >> 4;
    const int m0 = blockIdx.x * 128;
    const int n0 = blockIdx.y * 128;

    const int lrow = t >> 1;
    const int lk   = (t & 1) * 4;

    const float* Ag = A + (size_t)(m0 + lrow) * K + lk;
    const float* Wg = W + (size_t)(n0 + lrow) * K + lk;

    float acc[8][8];
#pragma unroll
    for (int r = 0; r < 8; r++)
#pragma unroll
        for (int c = 0; c < 8; c++) acc[r][c] = 0.0f;

    for (int kk = 0; kk < K; kk += 8) {
        float4 av = *reinterpret_cast<const float4*>(Ag + kk);
        float4 wv = *reinterpret_cast<const float4*>(Wg + kk);
        __syncthreads();
        As[lk + 0][lrow] = av.x; As[lk + 1][lrow] = av.y;
        As[lk + 2][lrow] = av.z; As[lk + 3][lrow] = av.w;
        Ws[lk + 0][lrow] = wv.x; Ws[lk + 1][lrow] = wv.y;
        Ws[lk + 2][lrow] = wv.z; Ws[lk + 3][lrow] = wv.w;
        __syncthreads();
#pragma unroll
        for (int k = 0; k < 8; k++) {
            float a[8], b[8];
#pragma unroll
            for (int r = 0; r < 8; r++) a[r] = As[k][tx + 16 * r];
#pragma unroll
            for (int c = 0; c < 8; c++) b[c] = Ws[k][ty + 16 * c];
#pragma unroll
            for (int r = 0; r < 8; r++)
#pragma unroll
                for (int c = 0; c < 8; c++) acc[r][c] += a[r] * b[c];
        }
    }

#pragma unroll
    for (int r = 0; r < 8; r++) {
        int m = m0 + tx + 16 * r;
#pragma unroll
        for (int c = 0; c < 8; c++) {
            int n = n0 + ty + 16 * c;
            float v = acc[r][c] + bias[n];
            if (TANH) v = tanh_fast(v);
            C[(size_t)m * N + n] = v;
        }
    }
}

// ------------- GEMM3 + bias + normalize; writes out, nrm(f32), nB(bf16), zeros res
__global__ void __launch_bounds__(256) out_norm_kernel(
    const float* __restrict__ A, const float* __restrict__ W3,
    const float* __restrict__ b3, float* __restrict__ res)
{
    __shared__ __align__(16) float As[16][68];
    __shared__ __align__(16) float Ws[16][68];
    __shared__ __align__(16) float outS[64][68];
    __shared__ float rs[64];

    const int t  = threadIdx.x;
    const int tx = t & 15;
    const int ty = t >> 4;
    const int i0 = blockIdx.x * 64;
    const int K  = 256;

    const int lrow = t >> 2;
    const int lk   = (t & 3) * 4;

    float acc[4][4];
#pragma unroll
    for (int r = 0; r < 4; r++)
#pragma unroll
        for (int c = 0; c < 4; c++) acc[r][c] = 0.0f;

    for (int kk = 0; kk < K; kk += 16) {
        float4 av = *reinterpret_cast<const float4*>(A + (size_t)(i0 + lrow) * K + kk + lk);
        float4 wv = *reinterpret_cast<const float4*>(W3 + (size_t)lrow * K + kk + lk);
        __syncthreads();
        As[lk + 0][lrow] = av.x; As[lk + 1][lrow] = av.y;
        As[lk + 2][lrow] = av.z; As[lk + 3][lrow] = av.w;
        Ws[lk + 0][lrow] = wv.x; Ws[lk + 1][lrow] = wv.y;
        Ws[lk + 2][lrow] = wv.z; Ws[lk + 3][lrow] = wv.w;
        __syncthreads();
#pragma unroll
        for (int k = 0; k < 16; k++) {
            float a[4], b[4];
#pragma unroll
            for (int r = 0; r < 4; r++) a[r] = As[k][tx + 16 * r];
#pragma unroll
            for (int c = 0; c < 4; c++) b[c] = Ws[k][ty + 16 * c];
#pragma unroll
            for (int r = 0; r < 4; r++)
#pragma unroll
                for (int c = 0; c < 4; c++) acc[r][c] += a[r] * b[c];
        }
    }

#pragma unroll
    for (int r = 0; r < 4; r++)
#pragma unroll
        for (int c = 0; c < 4; c++)
            outS[tx + 16 * r][ty + 16 * c] = acc[r][c] + b3[ty + 16 * c];
    __syncthreads();

    if (t < 64) {
        float s = 0.0f;
#pragma unroll
        for (int c = 0; c < 64; c++) { float v = outS[t][c]; s += v * v; }
        rs[t] = 1.0f / (sqrtf(s) + 1e-12f);
    }
    __syncthreads();

#pragma unroll
    for (int q = 0; q < 16; q++) {
        int idx = t + 256 * q;
        int i = idx >> 6, c = idx & 63;
        size_t g = (size_t)(i0 + i) * DOUT + c;
        float v = outS[i][c];
        float nv = v * rs[i];
        g_out[g] = v;
        g_nrm[g] = nv;
        g_nB[g]  = __float2bfloat16(nv);
        res[g]   = 0.0f;
    }
}

// ------------- fid: bf16 mma Gram filter + fp32 recheck + sparse accumulate ----
// 128x128 tile, K=64. 8 warps: warp_m = wid&1 (64 rows), warp_n = wid>>1 (32 cols).
#define JSPLIT 8
#define THR      0.9f
#define THR_CAND 0.88f

__global__ void __launch_bounds__(256) fid_kernel(float* __restrict__ res)
{
    __shared__ __align__(16) __nv_bfloat16 At[128 * 72];   // 18 KB, 144B row stride
    __shared__ __align__(16) __nv_bfloat16 Bt[128 * 72];   // 18 KB
    __shared__ unsigned long long maskS[128][2];           //  2 KB

    const int t    = threadIdx.x;
    const int lane = t & 31;
    const int wid  = t >> 5;
    const int warp_m = wid & 1;        // 0..1  -> 64-row slab
    const int warp_n = wid >> 1;       // 0..3  -> 32-col slab
    const int i0 = blockIdx.x * 128;
    const int jb = blockIdx.y * (BATCH / JSPLIT);
    const int je = jb + (BATCH / JSPLIT);

    // load A tile: 128 rows x 64 bf16 (row = 8 x 16B chunks)
#pragma unroll
    for (int q = 0; q < 4; q++) {
        int idx = t + 256 * q;
        int r = idx >> 3, c = idx & 7;
        float4 v = *reinterpret_cast<const float4*>(g_nB + (size_t)(i0 + r) * 64 + c * 8);
        *reinterpret_cast<float4*>(At + r * 72 + c * 8) = v;
    }

    // A fragment smem addresses (fixed per thread, advance k by +16 elems)
    const unsigned at_base = smem_u32(At);
    const unsigned bt_base = smem_u32(Bt);

    const int my_i = t >> 1;           // accumulate ownership: row 0..127
    const int cb   = (t & 1) * 32;     // 32-col slice
    float facc[32];
#pragma unroll
    for (int c = 0; c < 32; c++) facc[c] = 0.0f;

    for (int j0 = jb; j0 < je; j0 += 128) {
        __syncthreads();               // prev accumulate done; At ready (iter 0)
        if (t < 128) { maskS[t][0] = 0ULL; maskS[t][1] = 0ULL; }
#pragma unroll
        for (int q = 0; q < 4; q++) {
            int idx = t + 256 * q;
            int r = idx >> 3, c = idx & 7;
            float4 v = *reinterpret_cast<const float4*>(g_nB + (size_t)(j0 + r) * 64 + c * 8);
            *reinterpret_cast<float4*>(Bt + r * 72 + c * 8) = v;
        }
        __syncthreads();

        float acc[4][4][4];
#pragma unroll
        for (int mt = 0; mt < 4; mt++)
#pragma unroll
            for (int nt = 0; nt < 4; nt++)
#pragma unroll
                for (int r = 0; r < 4; r++) acc[mt][nt][r] = 0.0f;

#pragma unroll
        for (int ks = 0; ks < 4; ks++) {
            const int k0 = ks * 16;
            unsigned a[4][4];
#pragma unroll
            for (int mt = 0; mt < 4; mt++) {
                int row = warp_m * 64 + mt * 16 + (lane & 15);
                int kc  = k0 + (lane >> 4) * 8;
                unsigned addr = at_base + (unsigned)(row * 72 + kc) * 2u;
                asm volatile(
                    "ldmatrix.sync.aligned.m8n8.x4.shared.b16 {%0,%1,%2,%3}, [%4];"
                    : "=r"(a[mt][0]), "=r"(a[mt][1]), "=r"(a[mt][2]), "=r"(a[mt][3])
                    : "r"(addr));
            }
            unsigned b[2][4];
#pragma unroll
            for (int h = 0; h < 2; h++) {
                int grp  = lane >> 3;
                int nrow = warp_n * 32 + h * 16 + (grp >> 1) * 8 + (lane & 7);
                int kc   = k0 + (grp & 1) * 8;
                unsigned addr = bt_base + (unsigned)(nrow * 72 + kc) * 2u;
                asm volatile(
                    "ldmatrix.sync.aligned.m8n8.x4.shared.b16 {%0,%1,%2,%3}, [%4];"
                    : "=r"(b[h][0]), "=r"(b[h][1]), "=r"(b[h][2]), "=r"(b[h][3])
                    : "r"(addr));
            }
#pragma unroll
            for (int mt = 0; mt < 4; mt++)
#pragma unroll
                for (int nt = 0; nt < 4; nt++) {
                    unsigned b0 = b[nt >> 1][(nt & 1) * 2 + 0];
                    unsigned b1 = b[nt >> 1][(nt & 1) * 2 + 1];
                    asm volatile(
                        "mma.sync.aligned.m16n8k16.row.col.f32.bf16.bf16.f32 "
                        "{%0,%1,%2,%3}, {%4,%5,%6,%7}, {%8,%9}, {%0,%1,%2,%3};"
                        : "+f"(acc[mt][nt][0]), "+f"(acc[mt][nt][1]),
                          "+f"(acc[mt][nt][2]), "+f"(acc[mt][nt][3])
                        : "r"(a[mt][0]), "r"(a[mt][1]), "r"(a[mt][2]), "r"(a[mt][3]),
                          "r"(b0), "r"(b1));
                }
        }

        // candidate filter (margin-safe) + exact fp32 recheck -> bitmask
#pragma unroll
        for (int mt = 0; mt < 4; mt++)
#pragma unroll
            for (int nt = 0; nt < 4; nt++)
#pragma unroll
                for (int r = 0; r < 4; r++) {
                    float d = acc[mt][nt][r];
                    if (d * d >= THR_CAND) {
                        int m_loc = warp_m * 64 + mt * 16 + (lane >> 2) + ((r >> 1) ? 8 : 0);
                        int n_loc = warp_n * 32 + nt * 8 + (lane & 3) * 2 + (r & 1);
                        int gi = i0 + m_loc, gj = j0 + n_loc;
                        if (gi != gj) {
                            const float4* pa = reinterpret_cast<const float4*>(
                                g_nrm + (size_t)gi * DOUT);
                            const float4* pb = reinterpret_cast<const float4*>(
                                g_nrm + (size_t)gj * DOUT);
                            float s = 0.0f;
#pragma unroll
                            for (int q = 0; q < 16; q++) {
                                float4 xa = pa[q], xb = pb[q];
                                s += xa.x * xb.x + xa.y * xb.y +
                                     xa.z * xb.z + xa.w * xb.w;
                            }
                            if (s * s >= THR)
                                atomicOr(&maskS[m_loc][n_loc >> 6],
                                         1ULL << (n_loc & 63));
                        }
                    }
                }
        __syncthreads();

        // sparse accumulate: only rows with set bits touch g_out
#pragma unroll
        for (int w = 0; w < 2; w++) {
            unsigned long long m = maskS[my_i][w];
            while (m) {
                int j = __ffsll((long long)m) - 1;
                m &= m - 1;
                const float4* op = reinterpret_cast<const float4*>(
                    g_out + (size_t)(j0 + 64 * w + j) * DOUT + cb);
#pragma unroll
                for (int c4 = 0; c4 < 8; c4++) {
                    float4 v = op[c4];
                    facc[4 * c4 + 0] += v.x;
                    facc[4 * c4 + 1] += v.y;
                    facc[4 * c4 + 2] += v.z;
                    facc[4 * c4 + 3] += v.w;
                }
            }
        }
    }

    float* rp = res + (size_t)(i0 + my_i) * DOUT + cb;
#pragma unroll
    for (int c = 0; c < 32; c++) atomicAdd(&rp[c], facc[c]);
}

// ------------------------------- launch ----------------------------------------
extern "C" void kernel_launch(void* const* d_in, const int* in_sizes, int n_in,
                              void* d_out, int out_size)
{
    const float* x  = (const float*)d_in[0];
    const float* W1 = (const float*)d_in[1];
    const float* b1 = (const float*)d_in[2];
    const float* W2 = (const float*)d_in[3];
    const float* b2 = (const float*)d_in[4];
    const float* W3 = (const float*)d_in[5];
    const float* b3 = (const float*)d_in[6];
    float* out = (float*)d_out;

    float *h1p, *h2p;
    cudaGetSymbolAddress((void**)&h1p, g_h1);
    cudaGetSymbolAddress((void**)&h2p, g_h2);

    gemm_tanh_kernel<DIN, true><<<dim3(BATCH / 128, H1 / 128), 256>>>(
        x, W1, b1, h1p, H1);
    gemm_tanh_kernel<H1, true><<<dim3(BATCH / 128, H2 / 128), 256>>>(
        h1p, W2, b2, h2p, H2);
    out_norm_kernel<<<BATCH / 64, 256>>>(h2p, W3, b3, out);
    fid_kernel<<<dim3(BATCH / 128, JSPLIT), 256>>>(out);
}

// round 5
// speedup vs baseline: 1.7221x; 1.6246x over previous
#include <cuda_runtime.h>
#include <cuda_bf16.h>
#include <math.h>

// ---------------- scratch (device globals; no allocation allowed) -------------
#define BATCH 8192
#define DIN   256
#define H1    512
#define H2    256
#define DOUT  64

#define EDGE_CAP (1 << 21)   // 2M candidate pairs (16 MB) — far above expected ~0

__device__ float g_h1[BATCH * H1];              // 16.8 MB
__device__ float g_h2[BATCH * H2];              //  8.4 MB
__device__ float g_out[BATCH * DOUT];           //  2.1 MB  row-major [B][64]
__device__ float g_nrm[BATCH * DOUT];           //  2.1 MB  fp32 normed, row-major
__device__ __nv_bfloat16 g_nB[BATCH * DOUT];    //  1.0 MB  bf16 normed, row-major
__device__ int  g_edge_cnt;
__device__ int2 g_edges[EDGE_CAP];

__device__ __forceinline__ float tanh_fast(float x)
{
    float y;
    asm("tanh.approx.f32 %0, %1;" : "=f"(y) : "f"(x));
    return y;
}

__device__ __forceinline__ unsigned smem_u32(const void* p)
{
    return (unsigned)__cvta_generic_to_shared(p);
}

// ---------------- GEMM: C[M,N] = act(A[M,K] @ W[N,K]^T + b) ------------------
template <int K, bool TANH>
__global__ void __launch_bounds__(256) gemm_tanh_kernel(
    const float* __restrict__ A, const float* __restrict__ W,
    const float* __restrict__ bias, float* __restrict__ C, int N)
{
    __shared__ __align__(16) float As[8][132];
    __shared__ __align__(16) float Ws[8][132];

    const int t  = threadIdx.x;
    const int tx = t & 15;
    const int ty = t >> 4;
    const int m0 = blockIdx.x * 128;
    const int n0 = blockIdx.y * 128;

    const int lrow = t >> 1;
    const int lk   = (t & 1) * 4;

    const float* Ag = A + (size_t)(m0 + lrow) * K + lk;
    const float* Wg = W + (size_t)(n0 + lrow) * K + lk;

    float acc[8][8];
#pragma unroll
    for (int r = 0; r < 8; r++)
#pragma unroll
        for (int c = 0; c < 8; c++) acc[r][c] = 0.0f;

    for (int kk = 0; kk < K; kk += 8) {
        float4 av = *reinterpret_cast<const float4*>(Ag + kk);
        float4 wv = *reinterpret_cast<const float4*>(Wg + kk);
        __syncthreads();
        As[lk + 0][lrow] = av.x; As[lk + 1][lrow] = av.y;
        As[lk + 2][lrow] = av.z; As[lk + 3][lrow] = av.w;
        Ws[lk + 0][lrow] = wv.x; Ws[lk + 1][lrow] = wv.y;
        Ws[lk + 2][lrow] = wv.z; Ws[lk + 3][lrow] = wv.w;
        __syncthreads();
#pragma unroll
        for (int k = 0; k < 8; k++) {
            float a[8], b[8];
#pragma unroll
            for (int r = 0; r < 8; r++) a[r] = As[k][tx + 16 * r];
#pragma unroll
            for (int c = 0; c < 8; c++) b[c] = Ws[k][ty + 16 * c];
#pragma unroll
            for (int r = 0; r < 8; r++)
#pragma unroll
                for (int c = 0; c < 8; c++) acc[r][c] += a[r] * b[c];
        }
    }

#pragma unroll
    for (int r = 0; r < 8; r++) {
        int m = m0 + tx + 16 * r;
#pragma unroll
        for (int c = 0; c < 8; c++) {
            int n = n0 + ty + 16 * c;
            float v = acc[r][c] + bias[n];
            if (TANH) v = tanh_fast(v);
            C[(size_t)m * N + n] = v;
        }
    }
}

// ------------- GEMM3 + bias + normalize; writes out, nrm, nB; zeros res + cnt --
__global__ void __launch_bounds__(256) out_norm_kernel(
    const float* __restrict__ A, const float* __restrict__ W3,
    const float* __restrict__ b3, float* __restrict__ res)
{
    __shared__ __align__(16) float As[16][68];
    __shared__ __align__(16) float Ws[16][68];
    __shared__ __align__(16) float outS[64][68];
    __shared__ float rs[64];

    const int t  = threadIdx.x;
    const int tx = t & 15;
    const int ty = t >> 4;
    const int i0 = blockIdx.x * 64;
    const int K  = 256;

    if (blockIdx.x == 0 && t == 0) g_edge_cnt = 0;

    const int lrow = t >> 2;
    const int lk   = (t & 3) * 4;

    float acc[4][4];
#pragma unroll
    for (int r = 0; r < 4; r++)
#pragma unroll
        for (int c = 0; c < 4; c++) acc[r][c] = 0.0f;

    for (int kk = 0; kk < K; kk += 16) {
        float4 av = *reinterpret_cast<const float4*>(A + (size_t)(i0 + lrow) * K + kk + lk);
        float4 wv = *reinterpret_cast<const float4*>(W3 + (size_t)lrow * K + kk + lk);
        __syncthreads();
        As[lk + 0][lrow] = av.x; As[lk + 1][lrow] = av.y;
        As[lk + 2][lrow] = av.z; As[lk + 3][lrow] = av.w;
        Ws[lk + 0][lrow] = wv.x; Ws[lk + 1][lrow] = wv.y;
        Ws[lk + 2][lrow] = wv.z; Ws[lk + 3][lrow] = wv.w;
        __syncthreads();
#pragma unroll
        for (int k = 0; k < 16; k++) {
            float a[4], b[4];
#pragma unroll
            for (int r = 0; r < 4; r++) a[r] = As[k][tx + 16 * r];
#pragma unroll
            for (int c = 0; c < 4; c++) b[c] = Ws[k][ty + 16 * c];
#pragma unroll
            for (int r = 0; r < 4; r++)
#pragma unroll
                for (int c = 0; c < 4; c++) acc[r][c] += a[r] * b[c];
        }
    }

#pragma unroll
    for (int r = 0; r < 4; r++)
#pragma unroll
        for (int c = 0; c < 4; c++)
            outS[tx + 16 * r][ty + 16 * c] = acc[r][c] + b3[ty + 16 * c];
    __syncthreads();

    if (t < 64) {
        float s = 0.0f;
#pragma unroll
        for (int c = 0; c < 64; c++) { float v = outS[t][c]; s += v * v; }
        rs[t] = 1.0f / (sqrtf(s) + 1e-12f);
    }
    __syncthreads();

#pragma unroll
    for (int q = 0; q < 16; q++) {
        int idx = t + 256 * q;
        int i = idx >> 6, c = idx & 63;
        size_t g = (size_t)(i0 + i) * DOUT + c;
        float v = outS[i][c];
        float nv = v * rs[i];
        g_out[g] = v;
        g_nrm[g] = nv;
        g_nB[g]  = __float2bfloat16(nv);
        res[g]   = 0.0f;
    }
}

// ------------- fid: bf16 mma Gram + threshold scan -> edge list ----------------
// 128x128 tile, K=64. 8 warps: warp_m = wid&1 (64 rows), warp_n = wid>>1 (32 cols).
// Hot loop has NO accumulate machinery; candidates (|dot| >= sqrt(0.88)) are
// appended to g_edges for exact recheck + apply in edge_apply_kernel.
#define JSPLIT 8
#define CAND_ABS 0.93808315f   // sqrt(0.88); bf16 dot error << 0.9-0.88 margin

__global__ void __launch_bounds__(256, 2) fid_kernel()
{
    __shared__ __align__(16) __nv_bfloat16 At[128 * 72];   // 18 KB, 144B stride
    __shared__ __align__(16) __nv_bfloat16 Bt[128 * 72];   // 18 KB

    const int t    = threadIdx.x;
    const int lane = t & 31;
    const int wid  = t >> 5;
    const int warp_m = wid & 1;
    const int warp_n = wid >> 1;
    const int i0 = blockIdx.x * 128;
    const int jb = blockIdx.y * (BATCH / JSPLIT);
    const int je = jb + (BATCH / JSPLIT);

#pragma unroll
    for (int q = 0; q < 4; q++) {
        int idx = t + 256 * q;
        int r = idx >> 3, c = idx & 7;
        float4 v = *reinterpret_cast<const float4*>(g_nB + (size_t)(i0 + r) * 64 + c * 8);
        *reinterpret_cast<float4*>(At + r * 72 + c * 8) = v;
    }

    const unsigned at_base = smem_u32(At);
    const unsigned bt_base = smem_u32(Bt);

    for (int j0 = jb; j0 < je; j0 += 128) {
        __syncthreads();               // prev mma done with Bt; At visible (iter0)
#pragma unroll
        for (int q = 0; q < 4; q++) {
            int idx = t + 256 * q;
            int r = idx >> 3, c = idx & 7;
            float4 v = *reinterpret_cast<const float4*>(g_nB + (size_t)(j0 + r) * 64 + c * 8);
            *reinterpret_cast<float4*>(Bt + r * 72 + c * 8) = v;
        }
        __syncthreads();

        float acc[4][4][4];
#pragma unroll
        for (int mt = 0; mt < 4; mt++)
#pragma unroll
            for (int nt = 0; nt < 4; nt++)
#pragma unroll
                for (int r = 0; r < 4; r++) acc[mt][nt][r] = 0.0f;

#pragma unroll
        for (int ks = 0; ks < 4; ks++) {
            const int k0 = ks * 16;
            unsigned a[4][4];
#pragma unroll
            for (int mt = 0; mt < 4; mt++) {
                int row = warp_m * 64 + mt * 16 + (lane & 15);
                int kc  = k0 + (lane >> 4) * 8;
                unsigned addr = at_base + (unsigned)(row * 72 + kc) * 2u;
                asm volatile(
                    "ldmatrix.sync.aligned.m8n8.x4.shared.b16 {%0,%1,%2,%3}, [%4];"
                    : "=r"(a[mt][0]), "=r"(a[mt][1]), "=r"(a[mt][2]), "=r"(a[mt][3])
                    : "r"(addr));
            }
            unsigned b[2][4];
#pragma unroll
            for (int h = 0; h < 2; h++) {
                int grp  = lane >> 3;
                int nrow = warp_n * 32 + h * 16 + (grp >> 1) * 8 + (lane & 7);
                int kc   = k0 + (grp & 1) * 8;
                unsigned addr = bt_base + (unsigned)(nrow * 72 + kc) * 2u;
                asm volatile(
                    "ldmatrix.sync.aligned.m8n8.x4.shared.b16 {%0,%1,%2,%3}, [%4];"
                    : "=r"(b[h][0]), "=r"(b[h][1]), "=r"(b[h][2]), "=r"(b[h][3])
                    : "r"(addr));
            }
#pragma unroll
            for (int mt = 0; mt < 4; mt++)
#pragma unroll
                for (int nt = 0; nt < 4; nt++) {
                    unsigned b0 = b[nt >> 1][(nt & 1) * 2 + 0];
                    unsigned b1 = b[nt >> 1][(nt & 1) * 2 + 1];
                    asm volatile(
                        "mma.sync.aligned.m16n8k16.row.col.f32.bf16.bf16.f32 "
                        "{%0,%1,%2,%3}, {%4,%5,%6,%7}, {%8,%9}, {%0,%1,%2,%3};"
                        : "+f"(acc[mt][nt][0]), "+f"(acc[mt][nt][1]),
                          "+f"(acc[mt][nt][2]), "+f"(acc[mt][nt][3])
                        : "r"(a[mt][0]), "r"(a[mt][1]), "r"(a[mt][2]), "r"(a[mt][3]),
                          "r"(b0), "r"(b1));
                }
        }

        // threshold scan: rare hits appended to global edge list
#pragma unroll
        for (int mt = 0; mt < 4; mt++)
#pragma unroll
            for (int nt = 0; nt < 4; nt++)
#pragma unroll
                for (int r = 0; r < 4; r++) {
                    if (fabsf(acc[mt][nt][r]) >= CAND_ABS) {
                        int gi = i0 + warp_m * 64 + mt * 16 + (lane >> 2) + ((r >> 1) ? 8 : 0);
                        int gj = j0 + warp_n * 32 + nt * 8 + (lane & 3) * 2 + (r & 1);
                        if (gi != gj) {
                            int e = atomicAdd(&g_edge_cnt, 1);
                            if (e < EDGE_CAP) g_edges[e] = make_int2(gi, gj);
                        }
                    }
                }
    }
}

// ------------- edge apply: exact fp32 recheck + sparse accumulate --------------
__global__ void edge_apply_kernel(float* __restrict__ res)
{
    int n = g_edge_cnt;
    if (n > EDGE_CAP) n = EDGE_CAP;
    for (int e = blockIdx.x * blockDim.x + threadIdx.x; e < n;
         e += gridDim.x * blockDim.x) {
        int2 ed = g_edges[e];
        const float4* pa = reinterpret_cast<const float4*>(g_nrm + (size_t)ed.x * DOUT);
        const float4* pb = reinterpret_cast<const float4*>(g_nrm + (size_t)ed.y * DOUT);
        float s = 0.0f;
#pragma unroll
        for (int q = 0; q < 16; q++) {
            float4 xa = pa[q], xb = pb[q];
            s += xa.x * xb.x + xa.y * xb.y + xa.z * xb.z + xa.w * xb.w;
        }
        if (s * s >= 0.9f) {
            const float* oj = g_out + (size_t)ed.y * DOUT;
            float* ri = res + (size_t)ed.x * DOUT;
#pragma unroll
            for (int c = 0; c < DOUT; c++) atomicAdd(&ri[c], oj[c]);
        }
    }
}

// ------------------------------- launch ----------------------------------------
extern "C" void kernel_launch(void* const* d_in, const int* in_sizes, int n_in,
                              void* d_out, int out_size)
{
    const float* x  = (const float*)d_in[0];
    const float* W1 = (const float*)d_in[1];
    const float* b1 = (const float*)d_in[2];
    const float* W2 = (const float*)d_in[3];
    const float* b2 = (const float*)d_in[4];
    const float* W3 = (const float*)d_in[5];
    const float* b3 = (const float*)d_in[6];
    float* out = (float*)d_out;

    float *h1p, *h2p;
    cudaGetSymbolAddress((void**)&h1p, g_h1);
    cudaGetSymbolAddress((void**)&h2p, g_h2);

    gemm_tanh_kernel<DIN, true><<<dim3(BATCH / 128, H1 / 128), 256>>>(
        x, W1, b1, h1p, H1);
    gemm_tanh_kernel<H1, true><<<dim3(BATCH / 128, H2 / 128), 256>>>(
        h1p, W2, b2, h2p, H2);
    out_norm_kernel<<<BATCH / 64, 256>>>(h2p, W3, b3, out);
    fid_kernel<<<dim3(BATCH / 128, JSPLIT), 256>>>();
    edge_apply_kernel<<<256, 128>>>(out);
}

// round 6
// speedup vs baseline: 2.9536x; 1.7151x over previous
#include <cuda_runtime.h>
#include <cuda_bf16.h>
#include <math.h>

// ---------------- scratch (device globals; no allocation allowed) -------------
#define BATCH 8192
#define DIN   256
#define H1    512
#define H2    256
#define DOUT  64

#define EDGE_CAP (1 << 21)

__device__ __nv_bfloat16 g_xh[BATCH * DIN];     // split x
__device__ __nv_bfloat16 g_xl[BATCH * DIN];
__device__ __nv_bfloat16 g_w1h[H1 * DIN];
__device__ __nv_bfloat16 g_w1l[H1 * DIN];
__device__ __nv_bfloat16 g_w2h[H2 * H1];
__device__ __nv_bfloat16 g_w2l[H2 * H1];
__device__ __nv_bfloat16 g_h1h[BATCH * H1];     // split h1 (tanh output)
__device__ __nv_bfloat16 g_h1l[BATCH * H1];
__device__ float g_h2[BATCH * H2];              // fp32 h2
__device__ float g_out[BATCH * DOUT];
__device__ float g_nrm[BATCH * DOUT];
__device__ __nv_bfloat16 g_nB[BATCH * DOUT];
__device__ int  g_edge_cnt;
__device__ int2 g_edges[EDGE_CAP];

__device__ __forceinline__ float tanh_fast(float x)
{
    float y;
    asm("tanh.approx.f32 %0, %1;" : "=f"(y) : "f"(x));
    return y;
}

__device__ __forceinline__ unsigned smem_u32(const void* p)
{
    return (unsigned)__cvta_generic_to_shared(p);
}

// ---------------- fp32 -> bf16 hi/lo split -------------------------------------
__global__ void split_kernel(const float* __restrict__ src,
                             __nv_bfloat16* __restrict__ hi,
                             __nv_bfloat16* __restrict__ lo, int n)
{
    for (int i = blockIdx.x * blockDim.x + threadIdx.x; i < n;
         i += gridDim.x * blockDim.x) {
        float v = src[i];
        __nv_bfloat16 h = __float2bfloat16(v);
        hi[i] = h;
        lo[i] = __float2bfloat16(v - __bfloat162float(h));
    }
}

// ---------------- split-bf16 tensor GEMM: C = tanh(A @ W^T + b) ----------------
// BM=BN=128, BK=32, 256 thr, 8 warps (warp_m 0..1 x warp_n 0..3, tile 64x32).
// acc += Ah*Wh + Ah*Wl + Al*Wh  (3-term split, ~2^-16 relative error)
// OUT_MODE 0: write bf16 hi/lo (Ch,Cl). OUT_MODE 1: write fp32 (Cf).
#define SSTR 40   // smem row stride in bf16 (80B; 5r mod 8 -> conflict-free ldsm)

template <int K, int OUT_MODE>
__global__ void __launch_bounds__(256) gemm_split_kernel(
    const __nv_bfloat16* __restrict__ Ah, const __nv_bfloat16* __restrict__ Al,
    const __nv_bfloat16* __restrict__ Wh, const __nv_bfloat16* __restrict__ Wl,
    const float* __restrict__ bias,
    __nv_bfloat16* __restrict__ Ch, __nv_bfloat16* __restrict__ Cl,
    float* __restrict__ Cf, int N)
{
    __shared__ __align__(16) __nv_bfloat16 sAh[128 * SSTR];
    __shared__ __align__(16) __nv_bfloat16 sAl[128 * SSTR];
    __shared__ __align__(16) __nv_bfloat16 sWh[128 * SSTR];
    __shared__ __align__(16) __nv_bfloat16 sWl[128 * SSTR];

    const int t    = threadIdx.x;
    const int lane = t & 31;
    const int wid  = t >> 5;
    const int warp_m = wid & 1;
    const int warp_n = wid >> 1;
    const int i0 = blockIdx.x * 128;
    const int n0 = blockIdx.y * 128;

    const unsigned ah_base = smem_u32(sAh);
    const unsigned al_base = smem_u32(sAl);
    const unsigned wh_base = smem_u32(sWh);
    const unsigned wl_base = smem_u32(sWl);

    float acc[4][4][4];
#pragma unroll
    for (int mt = 0; mt < 4; mt++)
#pragma unroll
        for (int nt = 0; nt < 4; nt++)
#pragma unroll
            for (int r = 0; r < 4; r++) acc[mt][nt][r] = 0.0f;

    for (int kk = 0; kk < K; kk += 32) {
        __syncthreads();
#pragma unroll
        for (int q = 0; q < 2; q++) {
            int idx = t + 256 * q;
            int r = idx >> 2, c = (idx & 3) * 8;
            size_t ga = (size_t)(i0 + r) * K + kk + c;
            size_t gw = (size_t)(n0 + r) * K + kk + c;
            *reinterpret_cast<float4*>(sAh + r * SSTR + c) =
                *reinterpret_cast<const float4*>(Ah + ga);
            *reinterpret_cast<float4*>(sAl + r * SSTR + c) =
                *reinterpret_cast<const float4*>(Al + ga);
            *reinterpret_cast<float4*>(sWh + r * SSTR + c) =
                *reinterpret_cast<const float4*>(Wh + gw);
            *reinterpret_cast<float4*>(sWl + r * SSTR + c) =
                *reinterpret_cast<const float4*>(Wl + gw);
        }
        __syncthreads();

#pragma unroll
        for (int ks = 0; ks < 2; ks++) {
            const int k0 = ks * 16;
            unsigned ah[4][4], al[4][4];
#pragma unroll
            for (int mt = 0; mt < 4; mt++) {
                int row = warp_m * 64 + mt * 16 + (lane & 15);
                int kc  = k0 + (lane >> 4) * 8;
                unsigned off = (unsigned)(row * SSTR + kc) * 2u;
                asm volatile(
                    "ldmatrix.sync.aligned.m8n8.x4.shared.b16 {%0,%1,%2,%3}, [%4];"
                    : "=r"(ah[mt][0]), "=r"(ah[mt][1]), "=r"(ah[mt][2]), "=r"(ah[mt][3])
                    : "r"(ah_base + off));
                asm volatile(
                    "ldmatrix.sync.aligned.m8n8.x4.shared.b16 {%0,%1,%2,%3}, [%4];"
                    : "=r"(al[mt][0]), "=r"(al[mt][1]), "=r"(al[mt][2]), "=r"(al[mt][3])
                    : "r"(al_base + off));
            }
            unsigned bh[2][4], bl[2][4];
#pragma unroll
            for (int h = 0; h < 2; h++) {
                int grp  = lane >> 3;
                int nrow = warp_n * 32 + h * 16 + (grp >> 1) * 8 + (lane & 7);
                int kc   = k0 + (grp & 1) * 8;
                unsigned off = (unsigned)(nrow * SSTR + kc) * 2u;
                asm volatile(
                    "ldmatrix.sync.aligned.m8n8.x4.shared.b16 {%0,%1,%2,%3}, [%4];"
                    : "=r"(bh[h][0]), "=r"(bh[h][1]), "=r"(bh[h][2]), "=r"(bh[h][3])
                    : "r"(wh_base + off));
                asm volatile(
                    "ldmatrix.sync.aligned.m8n8.x4.shared.b16 {%0,%1,%2,%3}, [%4];"
                    : "=r"(bl[h][0]), "=r"(bl[h][1]), "=r"(bl[h][2]), "=r"(bl[h][3])
                    : "r"(wl_base + off));
            }
#pragma unroll
            for (int mt = 0; mt < 4; mt++)
#pragma unroll
                for (int nt = 0; nt < 4; nt++) {
                    int hh = nt >> 1, p = (nt & 1) * 2;
#define MMA_BF16(AF, B0, B1)                                              \
    asm volatile(                                                          \
        "mma.sync.aligned.m16n8k16.row.col.f32.bf16.bf16.f32 "            \
        "{%0,%1,%2,%3}, {%4,%5,%6,%7}, {%8,%9}, {%0,%1,%2,%3};"           \
        : "+f"(acc[mt][nt][0]), "+f"(acc[mt][nt][1]),                      \
          "+f"(acc[mt][nt][2]), "+f"(acc[mt][nt][3])                       \
        : "r"(AF[mt][0]), "r"(AF[mt][1]), "r"(AF[mt][2]), "r"(AF[mt][3]), \
          "r"(B0), "r"(B1))
                    MMA_BF16(ah, bh[hh][p], bh[hh][p + 1]);
                    MMA_BF16(ah, bl[hh][p], bl[hh][p + 1]);
                    MMA_BF16(al, bh[hh][p], bh[hh][p + 1]);
#undef MMA_BF16
                }
        }
    }

    // epilogue: bias + tanh + store
#pragma unroll
    for (int mt = 0; mt < 4; mt++)
#pragma unroll
        for (int nt = 0; nt < 4; nt++) {
            int gm = i0 + warp_m * 64 + mt * 16 + (lane >> 2);
            int gn = n0 + warp_n * 32 + nt * 8 + (lane & 3) * 2;
            float bv0 = bias[gn], bv1 = bias[gn + 1];
            float v00 = tanh_fast(acc[mt][nt][0] + bv0);
            float v01 = tanh_fast(acc[mt][nt][1] + bv1);
            float v10 = tanh_fast(acc[mt][nt][2] + bv0);
            float v11 = tanh_fast(acc[mt][nt][3] + bv1);
            if (OUT_MODE == 0) {
                __nv_bfloat16 h00 = __float2bfloat16(v00);
                __nv_bfloat16 h01 = __float2bfloat16(v01);
                __nv_bfloat16 h10 = __float2bfloat16(v10);
                __nv_bfloat16 h11 = __float2bfloat16(v11);
                *reinterpret_cast<__nv_bfloat162*>(Ch + (size_t)gm * N + gn) =
                    __nv_bfloat162(h00, h01);
                *reinterpret_cast<__nv_bfloat162*>(Ch + (size_t)(gm + 8) * N + gn) =
                    __nv_bfloat162(h10, h11);
                *reinterpret_cast<__nv_bfloat162*>(Cl + (size_t)gm * N + gn) =
                    __nv_bfloat162(__float2bfloat16(v00 - __bfloat162float(h00)),
                                   __float2bfloat16(v01 - __bfloat162float(h01)));
                *reinterpret_cast<__nv_bfloat162*>(Cl + (size_t)(gm + 8) * N + gn) =
                    __nv_bfloat162(__float2bfloat16(v10 - __bfloat162float(h10)),
                                   __float2bfloat16(v11 - __bfloat162float(h11)));
            } else {
                *reinterpret_cast<float2*>(Cf + (size_t)gm * N + gn) =
                    make_float2(v00, v01);
                *reinterpret_cast<float2*>(Cf + (size_t)(gm + 8) * N + gn) =
                    make_float2(v10, v11);
            }
        }
}

// ------------- GEMM3 + bias + normalize; writes out, nrm, nB; zeros res + cnt --
__global__ void __launch_bounds__(256) out_norm_kernel(
    const float* __restrict__ A, const float* __restrict__ W3,
    const float* __restrict__ b3, float* __restrict__ res)
{
    __shared__ __align__(16) float As[16][68];
    __shared__ __align__(16) float Ws[16][68];
    __shared__ __align__(16) float outS[64][68];
    __shared__ float rs[64];

    const int t  = threadIdx.x;
    const int tx = t & 15;
    const int ty = t >> 4;
    const int i0 = blockIdx.x * 64;
    const int K  = 256;

    if (blockIdx.x == 0 && t == 0) g_edge_cnt = 0;

    const int lrow = t >> 2;
    const int lk   = (t & 3) * 4;

    float acc[4][4];
#pragma unroll
    for (int r = 0; r < 4; r++)
#pragma unroll
        for (int c = 0; c < 4; c++) acc[r][c] = 0.0f;

    for (int kk = 0; kk < K; kk += 16) {
        float4 av = *reinterpret_cast<const float4*>(A + (size_t)(i0 + lrow) * K + kk + lk);
        float4 wv = *reinterpret_cast<const float4*>(W3 + (size_t)lrow * K + kk + lk);
        __syncthreads();
        As[lk + 0][lrow] = av.x; As[lk + 1][lrow] = av.y;
        As[lk + 2][lrow] = av.z; As[lk + 3][lrow] = av.w;
        Ws[lk + 0][lrow] = wv.x; Ws[lk + 1][lrow] = wv.y;
        Ws[lk + 2][lrow] = wv.z; Ws[lk + 3][lrow] = wv.w;
        __syncthreads();
#pragma unroll
        for (int k = 0; k < 16; k++) {
            float a[4], b[4];
#pragma unroll
            for (int r = 0; r < 4; r++) a[r] = As[k][tx + 16 * r];
#pragma unroll
            for (int c = 0; c < 4; c++) b[c] = Ws[k][ty + 16 * c];
#pragma unroll
            for (int r = 0; r < 4; r++)
#pragma unroll
                for (int c = 0; c < 4; c++) acc[r][c] += a[r] * b[c];
        }
    }

#pragma unroll
    for (int r = 0; r < 4; r++)
#pragma unroll
        for (int c = 0; c < 4; c++)
            outS[tx + 16 * r][ty + 16 * c] = acc[r][c] + b3[ty + 16 * c];
    __syncthreads();

    if (t < 64) {
        float s = 0.0f;
#pragma unroll
        for (int c = 0; c < 64; c++) { float v = outS[t][c]; s += v * v; }
        rs[t] = 1.0f / (sqrtf(s) + 1e-12f);
    }
    __syncthreads();

#pragma unroll
    for (int q = 0; q < 16; q++) {
        int idx = t + 256 * q;
        int i = idx >> 6, c = idx & 63;
        size_t g = (size_t)(i0 + i) * DOUT + c;
        float v = outS[i][c];
        float nv = v * rs[i];
        g_out[g] = v;
        g_nrm[g] = nv;
        g_nB[g]  = __float2bfloat16(nv);
        res[g]   = 0.0f;
    }
}

// ------------- fid: bf16 mma Gram + threshold scan -> edge list ----------------
#define JSPLIT 8
#define CAND_ABS 0.93808315f   // sqrt(0.88)

__global__ void __launch_bounds__(256, 2) fid_kernel()
{
    __shared__ __align__(16) __nv_bfloat16 At[128 * 72];
    __shared__ __align__(16) __nv_bfloat16 Bt[128 * 72];

    const int t    = threadIdx.x;
    const int lane = t & 31;
    const int wid  = t >> 5;
    const int warp_m = wid & 1;
    const int warp_n = wid >> 1;
    const int i0 = blockIdx.x * 128;
    const int jb = blockIdx.y * (BATCH / JSPLIT);
    const int je = jb + (BATCH / JSPLIT);

#pragma unroll
    for (int q = 0; q < 4; q++) {
        int idx = t + 256 * q;
        int r = idx >> 3, c = idx & 7;
        float4 v = *reinterpret_cast<const float4*>(g_nB + (size_t)(i0 + r) * 64 + c * 8);
        *reinterpret_cast<float4*>(At + r * 72 + c * 8) = v;
    }

    const unsigned at_base = smem_u32(At);
    const unsigned bt_base = smem_u32(Bt);

    for (int j0 = jb; j0 < je; j0 += 128) {
        __syncthreads();
#pragma unroll
        for (int q = 0; q < 4; q++) {
            int idx = t + 256 * q;
            int r = idx >> 3, c = idx & 7;
            float4 v = *reinterpret_cast<const float4*>(g_nB + (size_t)(j0 + r) * 64 + c * 8);
            *reinterpret_cast<float4*>(Bt + r * 72 + c * 8) = v;
        }
        __syncthreads();

        float acc[4][4][4];
#pragma unroll
        for (int mt = 0; mt < 4; mt++)
#pragma unroll
            for (int nt = 0; nt < 4; nt++)
#pragma unroll
                for (int r = 0; r < 4; r++) acc[mt][nt][r] = 0.0f;

#pragma unroll
        for (int ks = 0; ks < 4; ks++) {
            const int k0 = ks * 16;
            unsigned a[4][4];
#pragma unroll
            for (int mt = 0; mt < 4; mt++) {
                int row = warp_m * 64 + mt * 16 + (lane & 15);
                int kc  = k0 + (lane >> 4) * 8;
                unsigned addr = at_base + (unsigned)(row * 72 + kc) * 2u;
                asm volatile(
                    "ldmatrix.sync.aligned.m8n8.x4.shared.b16 {%0,%1,%2,%3}, [%4];"
                    : "=r"(a[mt][0]), "=r"(a[mt][1]), "=r"(a[mt][2]), "=r"(a[mt][3])
                    : "r"(addr));
            }
            unsigned b[2][4];
#pragma unroll
            for (int h = 0; h < 2; h++) {
                int grp  = lane >> 3;
                int nrow = warp_n * 32 + h * 16 + (grp >> 1) * 8 + (lane & 7);
                int kc   = k0 + (grp & 1) * 8;
                unsigned addr = bt_base + (unsigned)(nrow * 72 + kc) * 2u;
                asm volatile(
                    "ldmatrix.sync.aligned.m8n8.x4.shared.b16 {%0,%1,%2,%3}, [%4];"
                    : "=r"(b[h][0]), "=r"(b[h][1]), "=r"(b[h][2]), "=r"(b[h][3])
                    : "r"(addr));
            }
#pragma unroll
            for (int mt = 0; mt < 4; mt++)
#pragma unroll
                for (int nt = 0; nt < 4; nt++) {
                    unsigned b0 = b[nt >> 1][(nt & 1) * 2 + 0];
                    unsigned b1 = b[nt >> 1][(nt & 1) * 2 + 1];
                    asm volatile(
                        "mma.sync.aligned.m16n8k16.row.col.f32.bf16.bf16.f32 "
                        "{%0,%1,%2,%3}, {%4,%5,%6,%7}, {%8,%9}, {%0,%1,%2,%3};"
                        : "+f"(acc[mt][nt][0]), "+f"(acc[mt][nt][1]),
                          "+f"(acc[mt][nt][2]), "+f"(acc[mt][nt][3])
                        : "r"(a[mt][0]), "r"(a[mt][1]), "r"(a[mt][2]), "r"(a[mt][3]),
                          "r"(b0), "r"(b1));
                }
        }

#pragma unroll
        for (int mt = 0; mt < 4; mt++)
#pragma unroll
            for (int nt = 0; nt < 4; nt++)
#pragma unroll
                for (int r = 0; r < 4; r++) {
                    if (fabsf(acc[mt][nt][r]) >= CAND_ABS) {
                        int gi = i0 + warp_m * 64 + mt * 16 + (lane >> 2) + ((r >> 1) ? 8 : 0);
                        int gj = j0 + warp_n * 32 + nt * 8 + (lane & 3) * 2 + (r & 1);
                        if (gi != gj) {
                            int e = atomicAdd(&g_edge_cnt, 1);
                            if (e < EDGE_CAP) g_edges[e] = make_int2(gi, gj);
                        }
                    }
                }
    }
}

// ------------- edge apply: exact fp32 recheck + sparse accumulate --------------
__global__ void edge_apply_kernel(float* __restrict__ res)
{
    int n = g_edge_cnt;
    if (n > EDGE_CAP) n = EDGE_CAP;
    for (int e = blockIdx.x * blockDim.x + threadIdx.x; e < n;
         e += gridDim.x * blockDim.x) {
        int2 ed = g_edges[e];
        const float4* pa = reinterpret_cast<const float4*>(g_nrm + (size_t)ed.x * DOUT);
        const float4* pb = reinterpret_cast<const float4*>(g_nrm + (size_t)ed.y * DOUT);
        float s = 0.0f;
#pragma unroll
        for (int q = 0; q < 16; q++) {
            float4 xa = pa[q], xb = pb[q];
            s += xa.x * xb.x + xa.y * xb.y + xa.z * xb.z + xa.w * xb.w;
        }
        if (s * s >= 0.9f) {
            const float* oj = g_out + (size_t)ed.y * DOUT;
            float* ri = res + (size_t)ed.x * DOUT;
#pragma unroll
            for (int c = 0; c < DOUT; c++) atomicAdd(&ri[c], oj[c]);
        }
    }
}

// ------------------------------- launch ----------------------------------------
extern "C" void kernel_launch(void* const* d_in, const int* in_sizes, int n_in,
                              void* d_out, int out_size)
{
    const float* x  = (const float*)d_in[0];
    const float* W1 = (const float*)d_in[1];
    const float* b1 = (const float*)d_in[2];
    const float* W2 = (const float*)d_in[3];
    const float* b2 = (const float*)d_in[4];
    const float* W3 = (const float*)d_in[5];
    const float* b3 = (const float*)d_in[6];
    float* out = (float*)d_out;

    __nv_bfloat16 *xh, *xl, *w1h, *w1l, *w2h, *w2l, *h1h, *h1l;
    float *h2p;
    cudaGetSymbolAddress((void**)&xh,  g_xh);
    cudaGetSymbolAddress((void**)&xl,  g_xl);
    cudaGetSymbolAddress((void**)&w1h, g_w1h);
    cudaGetSymbolAddress((void**)&w1l, g_w1l);
    cudaGetSymbolAddress((void**)&w2h, g_w2h);
    cudaGetSymbolAddress((void**)&w2l, g_w2l);
    cudaGetSymbolAddress((void**)&h1h, g_h1h);
    cudaGetSymbolAddress((void**)&h1l, g_h1l);
    cudaGetSymbolAddress((void**)&h2p, g_h2);

    split_kernel<<<512, 256>>>(x,  xh,  xl,  BATCH * DIN);
    split_kernel<<<128, 256>>>(W1, w1h, w1l, H1 * DIN);
    split_kernel<<<128, 256>>>(W2, w2h, w2l, H2 * H1);

    gemm_split_kernel<DIN, 0><<<dim3(BATCH / 128, H1 / 128), 256>>>(
        xh, xl, w1h, w1l, b1, h1h, h1l, nullptr, H1);
    gemm_split_kernel<H1, 1><<<dim3(BATCH / 128, H2 / 128), 256>>>(
        h1h, h1l, w2h, w2l, b2, nullptr, nullptr, h2p, H2);

    out_norm_kernel<<<BATCH / 64, 256>>>(h2p, W3, b3, out);
    fid_kernel<<<dim3(BATCH / 128, JSPLIT), 256>>>();
    edge_apply_kernel<<<256, 128>>>(out);
}